// round 3
// baseline (speedup 1.0000x reference)
#include <cuda_runtime.h>
#include <cuda_bf16.h>
#include <cstdint>

// Problem constants (from reference): B=16, T=4096, D=1024, DIMS={2,2,30}
#define NTOK   65536        // B*T
#define DDIM   1024
#define OUTC   34           // 2+2+30
#define NDEC   3

// Scratch (no cudaMalloc allowed): token lists bucketed by decoder + counters.
__device__ int g_cnt[NDEC];
__device__ int g_list[NDEC * NTOK];

// ---------------- packed f32x2 helpers (Blackwell) ----------------
static __device__ __forceinline__ unsigned long long ffma2(
    unsigned long long a, unsigned long long b, unsigned long long c) {
    unsigned long long d;
    asm("fma.rn.f32x2 %0, %1, %2, %3;" : "=l"(d) : "l"(a), "l"(b), "l"(c));
    return d;
}
static __device__ __forceinline__ float f2sum(unsigned long long v) {
    float lo, hi;
    asm("mov.b64 {%0, %1}, %2;" : "=f"(lo), "=f"(hi) : "l"(v));
    return lo + hi;
}

// ---------------- kernel 0: reset counters ----------------
__global__ void reset_kernel() {
    if (threadIdx.x < NDEC) g_cnt[threadIdx.x] = 0;
}

// ---------------- kernel 1: bucket tokens by decoder ----------------
__global__ void classify_kernel(const int* __restrict__ idx) {
    int t = blockIdx.x * blockDim.x + threadIdx.x;
    if (t < NTOK) {
        int d = idx[t];
        d = (d < 0) ? 0 : (d > 2 ? 2 : d);
        int p = atomicAdd(&g_cnt[d], 1);
        g_list[d * NTOK + p] = t;
    }
}

// ---------------- kernel 2: main compute ----------------
// Persistent blocks. Each warp processes a PAIR of same-decoder tokens:
//  - both x rows in registers (8x LDG.128 each, fully coalesced)
//  - W row shared-loads reused for both tokens
//  - packed f32x2 FMA, butterfly warp reduction, write all 34 channels.
#define SMEM_FLOATS (OUTC * DDIM + OUTC + 2)
#define SMEM_BYTES  (SMEM_FLOATS * 4)

__global__ __launch_bounds__(512, 1)
void multitask_kernel(const float* __restrict__ x,
                      const float* __restrict__ W0, const float* __restrict__ b0,
                      const float* __restrict__ W1, const float* __restrict__ b1,
                      const float* __restrict__ W2, const float* __restrict__ b2,
                      float* __restrict__ out) {
    extern __shared__ float smem[];
    float* sW = smem;                 // [34][1024]: rows 0-1 W0, 2-3 W1, 4-33 W2
    float* sb = smem + OUTC * DDIM;   // [34]

    // Stage weights into shared memory (float4 copies).
    {
        float4*       dW = (float4*)sW;
        const float4* s0 = (const float4*)W0;
        const float4* s1 = (const float4*)W1;
        const float4* s2 = (const float4*)W2;
        for (int i = threadIdx.x; i < 512; i += blockDim.x)  dW[i]        = s0[i];
        for (int i = threadIdx.x; i < 512; i += blockDim.x)  dW[512 + i]  = s1[i];
        for (int i = threadIdx.x; i < 7680; i += blockDim.x) dW[1024 + i] = s2[i];
        if (threadIdx.x < 2)  sb[threadIdx.x]      = b0[threadIdx.x];
        if (threadIdx.x < 2)  sb[2 + threadIdx.x]  = b1[threadIdx.x];
        if (threadIdx.x < 30) sb[4 + threadIdx.x]  = b2[threadIdx.x];
    }
    __syncthreads();

    const int lane  = threadIdx.x & 31;
    const int warp  = threadIdx.x >> 5;
    const int gw    = blockIdx.x * (blockDim.x >> 5) + warp;
    const int nwrp  = gridDim.x * (blockDim.x >> 5);

    const int c0 = g_cnt[0], c1 = g_cnt[1], c2 = g_cnt[2];
    const int P0 = (c0 + 1) >> 1, P1 = (c1 + 1) >> 1, P2 = (c2 + 1) >> 1;
    const int TP = P0 + P1 + P2;

    const ulonglong2* X = (const ulonglong2*)x;   // 16B chunks; 256 per row

    for (int p = gw; p < TP; p += nwrp) {
        int d, lp, cnt;
        if (p < P0)            { d = 0; lp = p;            cnt = c0; }
        else if (p < P0 + P1)  { d = 1; lp = p - P0;       cnt = c1; }
        else                   { d = 2; lp = p - P0 - P1;  cnt = c2; }
        const int base = (d == 0) ? 0 : (d == 1) ? 2 : 4;
        const int dim  = (d == 2) ? 30 : 2;

        const int tA = g_list[d * NTOK + 2 * lp];
        const bool hasB = (2 * lp + 1) < cnt;
        const int tB = hasB ? g_list[d * NTOK + 2 * lp + 1] : tA;

        // Load both x rows into registers (coalesced LDG.128).
        ulonglong2 xa[8], xb[8];
        const ulonglong2* XA = X + (size_t)tA * 256;
        const ulonglong2* XB = X + (size_t)tB * 256;
        #pragma unroll
        for (int i = 0; i < 8; i++) {
            xa[i] = XA[i * 32 + lane];
            xb[i] = XB[i * 32 + lane];
        }

        float rA0 = 0.f, rA1 = 0.f, rB0 = 0.f, rB1 = 0.f;
        const ulonglong2* Wp = (const ulonglong2*)(sW + base * DDIM);

        #pragma unroll 2
        for (int o = 0; o < dim; o++) {
            const ulonglong2* wrow = Wp + o * 256;  // 1024 floats = 256 x 16B
            unsigned long long aA0 = 0, aA1 = 0, aB0 = 0, aB1 = 0;
            #pragma unroll
            for (int i = 0; i < 8; i++) {
                ulonglong2 w = wrow[i * 32 + lane];  // LDS.128, conflict-free
                aA0 = ffma2(xa[i].x, w.x, aA0);
                aA1 = ffma2(xa[i].y, w.y, aA1);
                aB0 = ffma2(xb[i].x, w.x, aB0);
                aB1 = ffma2(xb[i].y, w.y, aB1);
            }
            float vA = f2sum(aA0) + f2sum(aA1);
            float vB = f2sum(aB0) + f2sum(aB1);
            #pragma unroll
            for (int s = 16; s > 0; s >>= 1) {
                vA += __shfl_xor_sync(0xFFFFFFFFu, vA, s);
                vB += __shfl_xor_sync(0xFFFFFFFFu, vB, s);
            }
            const int oi = base + o;
            const float bias = sb[oi];
            vA += bias; vB += bias;
            if (oi == lane)      { rA0 = vA; rB0 = vB; }
            if (oi - 32 == lane) { rA1 = vA; rB1 = vB; }
        }

        // Write all 34 channels (non-selected decoders = 0, matching reference).
        float* oA = out + (size_t)tA * OUTC;
        oA[lane] = rA0;
        if (lane < 2) oA[32 + lane] = rA1;
        if (hasB) {
            float* oB = out + (size_t)tB * OUTC;
            oB[lane] = rB0;
            if (lane < 2) oB[32 + lane] = rB1;
        }
    }
}

extern "C" void kernel_launch(void* const* d_in, const int* in_sizes, int n_in,
                              void* d_out, int out_size) {
    const float* x   = (const float*)d_in[0];
    const int*   idx = (const int*)  d_in[1];
    const float* W0  = (const float*)d_in[2];
    const float* b0  = (const float*)d_in[3];
    const float* W1  = (const float*)d_in[4];
    const float* b1  = (const float*)d_in[5];
    const float* W2  = (const float*)d_in[6];
    const float* b2  = (const float*)d_in[7];
    float* out = (float*)d_out;

    cudaFuncSetAttribute(multitask_kernel,
                         cudaFuncAttributeMaxDynamicSharedMemorySize, SMEM_BYTES);

    reset_kernel<<<1, 32>>>();
    classify_kernel<<<(NTOK + 511) / 512, 512>>>(idx);
    multitask_kernel<<<148, 512, SMEM_BYTES>>>(x, W0, b0, W1, b1, W2, b2, out);
}

// round 6
// speedup vs baseline: 1.2705x; 1.2705x over previous
#include <cuda_runtime.h>
#include <cuda_bf16.h>
#include <cstdint>

// Problem constants: B=16, T=4096, D=1024, DIMS={2,2,30}
#define NTOK   65536
#define DDIM   1024
#define OUTC   34
#define NDEC   3

__device__ int g_cnt[NDEC];
__device__ int g_list[NDEC * NTOK];

// ---------------- packed f32x2 helpers (Blackwell) ----------------
static __device__ __forceinline__ unsigned long long ffma2(
    unsigned long long a, unsigned long long b, unsigned long long c) {
    unsigned long long d;
    asm("fma.rn.f32x2 %0, %1, %2, %3;" : "=l"(d) : "l"(a), "l"(b), "l"(c));
    return d;
}
static __device__ __forceinline__ float f2sum(unsigned long long v) {
    float lo, hi;
    asm("mov.b64 {%0, %1}, %2;" : "=f"(lo), "=f"(hi) : "l"(v));
    return lo + hi;
}

// ---------------- kernel 0: reset counters ----------------
__global__ void reset_kernel() {
    if (threadIdx.x < NDEC) g_cnt[threadIdx.x] = 0;
}

// ---------------- kernel 1: bucket tokens (block-aggregated atomics) ----------------
__global__ void classify_kernel(const int* __restrict__ idx) {
    __shared__ int scnt[NDEC];
    __shared__ int sbase[NDEC];
    const int tid = threadIdx.x;
    if (tid < NDEC) scnt[tid] = 0;
    __syncthreads();

    const int t = blockIdx.x * blockDim.x + tid;
    int d = 0, my = 0;
    if (t < NTOK) {
        d = idx[t];
        d = (d < 0) ? 0 : (d > 2 ? 2 : d);
        my = atomicAdd(&scnt[d], 1);           // SMEM atomic, 3 addresses
    }
    __syncthreads();
    if (tid < NDEC) sbase[tid] = atomicAdd(&g_cnt[tid], scnt[tid]);  // 3 global atomics/block
    __syncthreads();
    if (t < NTOK) g_list[d * NTOK + sbase[d] + my] = t;
}

// ---------------- kernel 2: main compute ----------------
// Persistent blocks of 256 threads, 1 block/SM (W in SMEM = 139 KB).
// Each warp processes a QUAD of same-decoder tokens:
//   - 4 x rows in registers (32x LDG.128, coalesced)
//   - each W shared-row load reused 4x (halves LDS traffic vs pair version)
//   - packed f32x2 FMA; 4 interleaved butterfly reductions (latency-hidden).
#define SMEM_FLOATS (OUTC * DDIM + OUTC + 2)
#define SMEM_BYTES  (SMEM_FLOATS * 4)

__global__ __launch_bounds__(256, 1)
void multitask_kernel(const float* __restrict__ x,
                      const float* __restrict__ W0, const float* __restrict__ b0,
                      const float* __restrict__ W1, const float* __restrict__ b1,
                      const float* __restrict__ W2, const float* __restrict__ b2,
                      float* __restrict__ out) {
    extern __shared__ float smem[];
    float* sW = smem;                 // [34][1024]: rows 0-1 W0, 2-3 W1, 4-33 W2
    float* sb = smem + OUTC * DDIM;   // [34]

    {
        float4*       dW = (float4*)sW;
        const float4* s0 = (const float4*)W0;
        const float4* s1 = (const float4*)W1;
        const float4* s2 = (const float4*)W2;
        for (int i = threadIdx.x; i < 512; i += blockDim.x)  dW[i]        = s0[i];
        for (int i = threadIdx.x; i < 512; i += blockDim.x)  dW[512 + i]  = s1[i];
        for (int i = threadIdx.x; i < 7680; i += blockDim.x) dW[1024 + i] = s2[i];
        if (threadIdx.x < 2)  sb[threadIdx.x]      = b0[threadIdx.x];
        if (threadIdx.x < 2)  sb[2 + threadIdx.x]  = b1[threadIdx.x];
        if (threadIdx.x < 30) sb[4 + threadIdx.x]  = b2[threadIdx.x];
    }
    __syncthreads();

    const int lane  = threadIdx.x & 31;
    const int warp  = threadIdx.x >> 5;
    const int gw    = blockIdx.x * (blockDim.x >> 5) + warp;
    const int nwrp  = gridDim.x * (blockDim.x >> 5);

    const int c0 = g_cnt[0], c1 = g_cnt[1], c2 = g_cnt[2];
    const int P0 = (c0 + 3) >> 2, P1 = (c1 + 3) >> 2, P2 = (c2 + 3) >> 2;
    const int TP = P0 + P1 + P2;

    const ulonglong2* X = (const ulonglong2*)x;   // 16B chunks; 256 per row

    for (int p = gw; p < TP; p += nwrp) {
        int d, lp, cnt;
        if (p < P0)            { d = 0; lp = p;            cnt = c0; }
        else if (p < P0 + P1)  { d = 1; lp = p - P0;       cnt = c1; }
        else                   { d = 2; lp = p - P0 - P1;  cnt = c2; }
        const int base = (d == 0) ? 0 : (d == 1) ? 2 : 4;
        const int dim  = (d == 2) ? 30 : 2;

        const int q = 4 * lp;
        int  tok[4];
        bool has[4];
        #pragma unroll
        for (int i = 0; i < 4; i++) {
            int j = q + i;
            has[i] = (j < cnt);
            tok[i] = g_list[d * NTOK + (has[i] ? j : q)];
        }

        // 4 x rows into registers: 32x LDG.128 per warp, high MLP.
        ulonglong2 xr[4][8];
        #pragma unroll
        for (int i = 0; i < 4; i++) {
            const ulonglong2* XR = X + (size_t)tok[i] * 256;
            #pragma unroll
            for (int j = 0; j < 8; j++) xr[i][j] = XR[j * 32 + lane];
        }

        float r0[4] = {0.f, 0.f, 0.f, 0.f};
        float r1[4] = {0.f, 0.f, 0.f, 0.f};
        const ulonglong2* Wp = (const ulonglong2*)(sW + base * DDIM);

        #pragma unroll 2
        for (int o = 0; o < dim; o++) {
            const ulonglong2* wrow = Wp + o * 256;  // 1024 floats = 256 x 16B
            unsigned long long a0[4] = {0, 0, 0, 0};
            unsigned long long a1[4] = {0, 0, 0, 0};
            #pragma unroll
            for (int j = 0; j < 8; j++) {
                ulonglong2 w = wrow[j * 32 + lane];  // LDS.128, conflict-free
                #pragma unroll
                for (int i = 0; i < 4; i++) {
                    a0[i] = ffma2(xr[i][j].x, w.x, a0[i]);
                    a1[i] = ffma2(xr[i][j].y, w.y, a1[i]);
                }
            }
            float v[4];
            #pragma unroll
            for (int i = 0; i < 4; i++) v[i] = f2sum(a0[i]) + f2sum(a1[i]);
            // 4 interleaved butterfly reductions: SHFL latency of one chain
            // overlaps the FADDs of the others.
            #pragma unroll
            for (int s = 16; s > 0; s >>= 1) {
                #pragma unroll
                for (int i = 0; i < 4; i++)
                    v[i] += __shfl_xor_sync(0xFFFFFFFFu, v[i], s);
            }
            const int oi = base + o;
            const float bias = sb[oi];
            #pragma unroll
            for (int i = 0; i < 4; i++) {
                float vi = v[i] + bias;
                if (oi == lane)      r0[i] = vi;
                if (oi - 32 == lane) r1[i] = vi;
            }
        }

        // Write all 34 channels (non-selected decoders = 0, matching reference).
        #pragma unroll
        for (int i = 0; i < 4; i++) {
            if (has[i]) {
                float* o_ = out + (size_t)tok[i] * OUTC;
                o_[lane] = r0[i];
                if (lane < 2) o_[32 + lane] = r1[i];
            }
        }
    }
}

extern "C" void kernel_launch(void* const* d_in, const int* in_sizes, int n_in,
                              void* d_out, int out_size) {
    const float* x   = (const float*)d_in[0];
    const int*   idx = (const int*)  d_in[1];
    const float* W0  = (const float*)d_in[2];
    const float* b0  = (const float*)d_in[3];
    const float* W1  = (const float*)d_in[4];
    const float* b1  = (const float*)d_in[5];
    const float* W2  = (const float*)d_in[6];
    const float* b2  = (const float*)d_in[7];
    float* out = (float*)d_out;

    cudaFuncSetAttribute(multitask_kernel,
                         cudaFuncAttributeMaxDynamicSharedMemorySize, SMEM_BYTES);

    reset_kernel<<<1, 32>>>();
    classify_kernel<<<(NTOK + 511) / 512, 512>>>(idx);
    multitask_kernel<<<148, 256, SMEM_BYTES>>>(x, W0, b0, W1, b1, W2, b2, out);
}